// round 16
// baseline (speedup 1.0000x reference)
#include <cuda_runtime.h>
#include <cuda_fp16.h>
#include <math.h>
#include <stdint.h>

#define D_MODEL 2048
#define NHEAD   16
#define DKH     128
#define DFF     5632
#define SEQ     2048
#define BATCH   2
#define M_TOK   (BATCH*SEQ)   // 4096

// ---------------- scratch ----------------
__device__ float  g_xmid[(size_t)M_TOK*D_MODEL];
__device__ __half g_xn_h [(size_t)M_TOK*D_MODEL];
__device__ __half g_ctx_h[(size_t)M_TOK*D_MODEL];
__device__ __half g_ff_h [(size_t)M_TOK*DFF];
__device__ __half g_qh[(size_t)M_TOK*D_MODEL];
__device__ __half g_kh[(size_t)M_TOK*D_MODEL];
__device__ __half g_vh[(size_t)M_TOK*D_MODEL];
__device__ __half g_wq[(size_t)D_MODEL*D_MODEL];
__device__ __half g_wk[(size_t)D_MODEL*D_MODEL];
__device__ __half g_wv[(size_t)D_MODEL*D_MODEL];
__device__ __half g_wo[(size_t)D_MODEL*D_MODEL];
__device__ __half g_w1[(size_t)DFF*D_MODEL];
__device__ __half g_w2[(size_t)D_MODEL*DFF];
__device__ __half g_w3[(size_t)DFF*D_MODEL];
__device__ float  g_rsin[SEQ*64];
__device__ float  g_rcos[SEQ*64];

// ================= helpers =================
__device__ __forceinline__ void mma_f16(float* d, const uint32_t* a, const uint32_t* b) {
    asm volatile(
        "mma.sync.aligned.m16n8k16.row.col.f32.f16.f16.f32 "
        "{%0,%1,%2,%3}, {%4,%5,%6,%7}, {%8,%9}, {%0,%1,%2,%3};"
        : "+f"(d[0]), "+f"(d[1]), "+f"(d[2]), "+f"(d[3])
        : "r"(a[0]), "r"(a[1]), "r"(a[2]), "r"(a[3]),
          "r"(b[0]), "r"(b[1]));
}
__device__ __forceinline__ uint32_t smem_u32(const void* p) {
    uint32_t a;
    asm("{ .reg .u64 t; cvta.to.shared.u64 t, %1; cvt.u32.u64 %0, t; }"
        : "=r"(a) : "l"(p));
    return a;
}
__device__ __forceinline__ void cp_async16(uint32_t dst, const void* src) {
    asm volatile("cp.async.cg.shared.global [%0], [%1], 16;" :: "r"(dst), "l"(src));
}
__device__ __forceinline__ void cp_async16_ca(uint32_t dst, const void* src) {
    asm volatile("cp.async.ca.shared.global [%0], [%1], 16;" :: "r"(dst), "l"(src));
}
#define CP_COMMIT()  asm volatile("cp.async.commit_group;" ::: "memory")
#define CP_WAIT(N)   asm volatile("cp.async.wait_group %0;" :: "n"(N) : "memory")

__device__ __forceinline__ void ldsm_x4(uint32_t* r, uint32_t a) {
    asm volatile("ldmatrix.sync.aligned.m8n8.x4.shared.b16 {%0,%1,%2,%3}, [%4];"
                 : "=r"(r[0]), "=r"(r[1]), "=r"(r[2]), "=r"(r[3]) : "r"(a));
}
__device__ __forceinline__ void ldsm_x4_t(uint32_t* r, uint32_t a) {
    asm volatile("ldmatrix.sync.aligned.m8n8.x4.trans.shared.b16 {%0,%1,%2,%3}, [%4];"
                 : "=r"(r[0]), "=r"(r[1]), "=r"(r[2]), "=r"(r[3]) : "r"(a));
}
__device__ __forceinline__ uint32_t f22u(float a, float b) {
    __half2 h = __floats2half2_rn(a, b);
    return *(uint32_t*)&h;
}

// ---------------- fp32 -> fp16 convert ----------------
__global__ void f2h_kernel(const float4* __restrict__ in, __half2* __restrict__ out, int n4) {
    int i = blockIdx.x * blockDim.x + threadIdx.x;
    if (i >= n4) return;
    float4 v = in[i];
    out[2 * i]     = __floats2half2_rn(v.x, v.y);
    out[2 * i + 1] = __floats2half2_rn(v.z, v.w);
}

// ================= fp16 GEMM, 128x128 tiles, BK=64, 3-stage, 2 CTAs/SM ======
// A loads .ca (co-resident CTA pair shares the A panel); B loads .cg.
// Next stage issued BEFORE compute for extra latency slack.
#define GBM 128
#define GBN 128
#define LDH  72
#define GSTG 3
#define GEMM_SMEM (GSTG*(GBM+GBN)*LDH*2)

template<int EPI>
__device__ __forceinline__ void gemm_body(
        const __half* __restrict__ A,
        const __half* __restrict__ W,
        const void* __restrict__ res,
        void* __restrict__ CO,
        int M, int N, int K, int ropef) {
    extern __shared__ char smc[];
    __half* As = (__half*)smc;
    __half* Bs = As + GSTG * GBM * LDH;

    int tid  = threadIdx.x;
    int lane = tid & 31, wid = tid >> 5;
    int wmb = (wid >> 2) * 64, wnb = (wid & 3) * 32;
    int bm = blockIdx.y * GBM, bn = blockIdx.x * GBN;
    int m4 = lane >> 3, r8 = lane & 7;

    uint32_t as_base = smem_u32(As);
    uint32_t bs_base = smem_u32(Bs);

    auto issue_stage = [&](int tile, int stg) {
        uint32_t aoff = (uint32_t)stg * GBM * LDH * 2;
        uint32_t boff = (uint32_t)stg * GBN * LDH * 2;
        const __half* a2 = A + (size_t)bm * K + tile * 64;
        const __half* w2 = W + (size_t)bn * K + tile * 64;
#pragma unroll
        for (int i = 0; i < 4; i++) {
            int idx = tid + i * 256;
            int r = idx >> 3, c = (idx & 7) * 8;
            cp_async16_ca(as_base + aoff + (uint32_t)(r * LDH + c) * 2,
                          a2 + (size_t)r * K + c);
            cp_async16(bs_base + boff + (uint32_t)(r * LDH + c) * 2,
                       w2 + (size_t)r * K + c);
        }
    };

    int nk = K >> 6;
    issue_stage(0, 0); CP_COMMIT();
    issue_stage(1, 1); CP_COMMIT();

    float acc[4][4][4] = {};
    int qr = lane >> 2, qc = lane & 3;

    int stg = 0;
    for (int kt = 0; kt < nk; kt++) {
        CP_WAIT(1);
        __syncthreads();
        // issue next tile first (stage was freed by the barrier above)
        int nstg = stg + 2; if (nstg >= GSTG) nstg -= GSTG;
        if (kt + 2 < nk) issue_stage(kt + 2, nstg);
        CP_COMMIT();

        uint32_t aS = as_base + (uint32_t)stg * GBM * LDH * 2;
        uint32_t bS = bs_base + (uint32_t)stg * GBN * LDH * 2;
#pragma unroll
        for (int kh = 0; kh < 2; kh++) {
            uint32_t bf[4][4];
#pragma unroll
            for (int nt = 0; nt < 4; nt++) {
                int n0 = wnb + nt * 8 + r8;
                ldsm_x4(bf[nt], bS + (uint32_t)(n0 * LDH + kh * 32 + m4 * 8) * 2);
            }
#pragma unroll
            for (int k2 = 0; k2 < 2; k2++) {
                int ks = kh * 2 + k2;
                uint32_t af[4][4];
#pragma unroll
                for (int mt = 0; mt < 4; mt++) {
                    int r0 = wmb + mt * 16 + (m4 & 1) * 8 + r8;
                    ldsm_x4(af[mt], aS + (uint32_t)(r0 * LDH + ks * 16 + (m4 >> 1) * 8) * 2);
                }
#pragma unroll
                for (int mt = 0; mt < 4; mt++)
#pragma unroll
                    for (int nt = 0; nt < 4; nt++)
                        mma_f16(acc[mt][nt], af[mt], &bf[nt][2 * k2]);
            }
        }
        stg = stg + 1 == GSTG ? 0 : stg + 1;
    }

#pragma unroll
    for (int mt = 0; mt < 4; mt++) {
        int r0 = bm + wmb + mt * 16 + qr;
#pragma unroll
        for (int nt = 0; nt < 4; nt++) {
            int cc = bn + wnb + nt * 8 + 2 * qc;
            size_t i0 = (size_t)r0 * N + cc;
            size_t i1 = (size_t)(r0 + 8) * N + cc;
            if (EPI == 1) {
                const float* rf = (const float*)res;
                float* C = (float*)CO;
                float2 rr0 = *(const float2*)(rf + i0);
                float2 rr1 = *(const float2*)(rf + i1);
                *(float2*)(C + i0) = make_float2(acc[mt][nt][0] + rr0.x,
                                                 acc[mt][nt][1] + rr0.y);
                *(float2*)(C + i1) = make_float2(acc[mt][nt][2] + rr1.x,
                                                 acc[mt][nt][3] + rr1.y);
            } else {
                __half* C = (__half*)CO;
                float a0 = acc[mt][nt][0], a1 = acc[mt][nt][1];
                float a2 = acc[mt][nt][2], a3 = acc[mt][nt][3];
                if (ropef) {
                    int s0 = r0 & (SEQ - 1), s1 = (r0 + 8) & (SEQ - 1);
                    int j  = (cc & 127) >> 1;
                    float sn0 = g_rsin[s0 * 64 + j], cs0 = g_rcos[s0 * 64 + j];
                    float sn1 = g_rsin[s1 * 64 + j], cs1 = g_rcos[s1 * 64 + j];
                    *(__half2*)(C + i0) = __floats2half2_rn(a0 * cs0 - a1 * sn0,
                                                            a0 * sn0 + a1 * cs0);
                    *(__half2*)(C + i1) = __floats2half2_rn(a2 * cs1 - a3 * sn1,
                                                            a2 * sn1 + a3 * cs1);
                } else {
                    *(__half2*)(C + i0) = __floats2half2_rn(a0, a1);
                    *(__half2*)(C + i1) = __floats2half2_rn(a2, a3);
                }
            }
        }
    }
}

template<int EPI>
__global__ __launch_bounds__(256, 2) void gemm_mma(
        const __half* __restrict__ A, const __half* __restrict__ W,
        const void* __restrict__ res, void* __restrict__ CO,
        int M, int N, int K) {
    gemm_body<EPI>(A, W, res, CO, M, N, K, 0);
}

__global__ __launch_bounds__(256, 2) void gemm_qkv(const __half* __restrict__ A) {
    int z = blockIdx.z;
    const __half* W = z == 0 ? g_wq : (z == 1 ? g_wk : g_wv);
    __half* C = z == 0 ? g_qh : (z == 1 ? g_kh : g_vh);
    gemm_body<3>(A, W, nullptr, C, M_TOK, D_MODEL, D_MODEL, z < 2);
}

// ========== fused W1+W3 GEMM: ff = silu(W1 xn) * (W3 xn), BK=64 =============
__global__ __launch_bounds__(256, 2) void gemm_w13(const __half* __restrict__ A,
                                                   __half* __restrict__ FF) {
    extern __shared__ char smc[];
    __half* As  = (__half*)smc;
    __half* B1s = As  + GSTG * 128 * LDH;
    __half* B3s = B1s + GSTG * 64 * LDH;

    const int K = D_MODEL, N = DFF;
    int tid  = threadIdx.x;
    int lane = tid & 31, wid = tid >> 5;
    int wmb = (wid >> 2) * 64, wnb = (wid & 3) * 16;
    int bm = blockIdx.y * 128, bn = blockIdx.x * 64;
    int m4 = lane >> 3, r8 = lane & 7;

    uint32_t as_base  = smem_u32(As);
    uint32_t b1_base  = smem_u32(B1s);
    uint32_t b3_base  = smem_u32(B3s);

    auto issue_stage = [&](int tile, int stg) {
        uint32_t aoff = (uint32_t)stg * 128 * LDH * 2;
        uint32_t boff = (uint32_t)stg * 64 * LDH * 2;
        const __half* a2 = A    + (size_t)bm * K + tile * 64;
        const __half* w1 = g_w1 + (size_t)bn * K + tile * 64;
        const __half* w3 = g_w3 + (size_t)bn * K + tile * 64;
#pragma unroll
        for (int i = 0; i < 4; i++) {
            int idx = tid + i * 256;
            int r = idx >> 3, c = (idx & 7) * 8;
            cp_async16_ca(as_base + aoff + (uint32_t)(r * LDH + c) * 2,
                          a2 + (size_t)r * K + c);
        }
#pragma unroll
        for (int i = 0; i < 2; i++) {
            int idx = tid + i * 256;
            int r = idx >> 3, c = (idx & 7) * 8;
            uint32_t d = (uint32_t)(r * LDH + c) * 2;
            cp_async16(b1_base + boff + d, w1 + (size_t)r * K + c);
            cp_async16(b3_base + boff + d, w3 + (size_t)r * K + c);
        }
    };

    int nk = K >> 6;
    issue_stage(0, 0); CP_COMMIT();
    issue_stage(1, 1); CP_COMMIT();

    float acc1[4][2][4] = {}, acc3[4][2][4] = {};
    int qr = lane >> 2, qc = lane & 3;

    int stg = 0;
    for (int kt = 0; kt < nk; kt++) {
        CP_WAIT(1);
        __syncthreads();
        int nstg = stg + 2; if (nstg >= GSTG) nstg -= GSTG;
        if (kt + 2 < nk) issue_stage(kt + 2, nstg);
        CP_COMMIT();

        uint32_t aS  = as_base + (uint32_t)stg * 128 * LDH * 2;
        uint32_t b1S = b1_base + (uint32_t)stg * 64 * LDH * 2;
        uint32_t b3S = b3_base + (uint32_t)stg * 64 * LDH * 2;
#pragma unroll
        for (int kh = 0; kh < 2; kh++) {
            uint32_t b1f[2][4], b3f[2][4];
#pragma unroll
            for (int nt = 0; nt < 2; nt++) {
                int n0 = wnb + nt * 8 + r8;
                ldsm_x4(b1f[nt], b1S + (uint32_t)(n0 * LDH + kh * 32 + m4 * 8) * 2);
                ldsm_x4(b3f[nt], b3S + (uint32_t)(n0 * LDH + kh * 32 + m4 * 8) * 2);
            }
#pragma unroll
            for (int k2 = 0; k2 < 2; k2++) {
                int ks = kh * 2 + k2;
                uint32_t af[4][4];
#pragma unroll
                for (int mt = 0; mt < 4; mt++) {
                    int r0 = wmb + mt * 16 + (m4 & 1) * 8 + r8;
                    ldsm_x4(af[mt], aS + (uint32_t)(r0 * LDH + ks * 16 + (m4 >> 1) * 8) * 2);
                }
#pragma unroll
                for (int mt = 0; mt < 4; mt++)
#pragma unroll
                    for (int nt = 0; nt < 2; nt++) {
                        mma_f16(acc1[mt][nt], af[mt], &b1f[nt][2 * k2]);
                        mma_f16(acc3[mt][nt], af[mt], &b3f[nt][2 * k2]);
                    }
            }
        }
        stg = stg + 1 == GSTG ? 0 : stg + 1;
    }

#pragma unroll
    for (int mt = 0; mt < 4; mt++) {
        int r0 = bm + wmb + mt * 16 + qr;
#pragma unroll
        for (int nt = 0; nt < 2; nt++) {
            int cc = bn + wnb + nt * 8 + 2 * qc;
            size_t i0 = (size_t)r0 * N + cc;
            size_t i1 = (size_t)(r0 + 8) * N + cc;
            float a0 = acc1[mt][nt][0], a1 = acc1[mt][nt][1];
            float a2 = acc1[mt][nt][2], a3 = acc1[mt][nt][3];
            float v0 = acc3[mt][nt][0] * (a0 / (1.f + __expf(-a0)));
            float v1 = acc3[mt][nt][1] * (a1 / (1.f + __expf(-a1)));
            float v2 = acc3[mt][nt][2] * (a2 / (1.f + __expf(-a2)));
            float v3 = acc3[mt][nt][3] * (a3 / (1.f + __expf(-a3)));
            *(__half2*)(FF + i0) = __floats2half2_rn(v0, v1);
            *(__half2*)(FF + i1) = __floats2half2_rn(v2, v3);
        }
    }
}

// ---------------- RMSNorm (float4 loads, writes half) ----------------
__global__ void rmsnorm_kernel(const float* __restrict__ x,
                               const float* __restrict__ g,
                               __half* __restrict__ out) {
    int row = blockIdx.x;
    const float4* xr = (const float4*)(x + (size_t)row * D_MODEL);
    float4 v[2];
    v[0] = xr[threadIdx.x];
    v[1] = xr[threadIdx.x + 256];
    float s = v[0].x*v[0].x + v[0].y*v[0].y + v[0].z*v[0].z + v[0].w*v[0].w
            + v[1].x*v[1].x + v[1].y*v[1].y + v[1].z*v[1].z + v[1].w*v[1].w;
    __shared__ float red[32];
    for (int o = 16; o; o >>= 1) s += __shfl_down_sync(0xffffffffu, s, o);
    if ((threadIdx.x & 31) == 0) red[threadIdx.x >> 5] = s;
    __syncthreads();
    if (threadIdx.x < 32) {
        float t = (threadIdx.x < 8) ? red[threadIdx.x] : 0.f;
        for (int o = 4; o; o >>= 1) t += __shfl_down_sync(0xffffffffu, t, o);
        if (threadIdx.x == 0) red[0] = t;
    }
    __syncthreads();
    float rinv = rsqrtf(red[0] * (1.0f / D_MODEL) + 1e-5f);
    __half2* orow = (__half2*)(out + (size_t)row * D_MODEL);
    const float4* g4 = (const float4*)g;
#pragma unroll
    for (int i = 0; i < 2; i++) {
        float4 gv = g4[threadIdx.x + i * 256];
        orow[(threadIdx.x + i * 256) * 2]     =
            __floats2half2_rn(v[i].x * gv.x * rinv, v[i].y * gv.y * rinv);
        orow[(threadIdx.x + i * 256) * 2 + 1] =
            __floats2half2_rn(v[i].z * gv.z * rinv, v[i].w * gv.w * rinv);
    }
}

// ---------------- RoPE tables ----------------
__global__ void rope_table_kernel() {
    int idx = blockIdx.x * blockDim.x + threadIdx.x;
    if (idx >= SEQ * 64) return;
    int j = idx & 63, s = idx >> 6;
    double inv = exp(-(double)j * (9.210340371976184 / 64.0));
    double ang = fmod((double)s * inv, 6.283185307179586476925286766559);
    float fa = (float)ang;
    g_rsin[idx] = sinf(fa);
    g_rcos[idx] = cosf(fa);
}

// ---------------- fp16 flash attention: BQ=64, 128 threads, multi-CTA/SM ----
#define QLD 136
#define KLH 136
#define ATT_SMEM ((2*64*KLH + 2*64*KLH) * 2)

__global__ __launch_bounds__(128) void attn_f16(
        const __half* __restrict__ Q,
        const __half* __restrict__ K,
        const __half* __restrict__ V,
        __half* __restrict__ O) {
    extern __shared__ __half smh[];
    __half* Qst = smh;
    __half* Ksm = smh;
    __half* Vsm = Ksm + 2 * 64 * KLH;

    int tid = threadIdx.x;
    int lane = tid & 31, wid = tid >> 5;
    int qr = lane >> 2, qc = lane & 3;
    int bh = blockIdx.y;
    int b = bh >> 4, h = bh & 15;
    int qblk = gridDim.x - 1 - blockIdx.x;
    int q0 = qblk * 64;
    int nkb = qblk + 1;
    int m4 = lane >> 3;
    int r8 = lane & 7;

    for (int i = tid; i < 64 * 16; i += 128) {
        int r = i >> 4, c8 = (i & 15) * 8;
        *(uint4*)(Qst + r * QLD + c8) =
            *(const uint4*)(Q + (size_t)(b * SEQ + q0 + r) * D_MODEL + h * DKH + c8);
    }
    __syncthreads();
    uint32_t afq[8][4];
    {
        uint32_t qb_ = smem_u32(Qst);
        int row = wid * 16 + (m4 & 1) * 8 + r8;
#pragma unroll
        for (int ks = 0; ks < 8; ks++)
            ldsm_x4(afq[ks], qb_ + (uint32_t)(row * QLD + ks * 16 + (m4 >> 1) * 8) * 2);
    }
    __syncthreads();

    uint32_t ks_base = smem_u32(Ksm);
    uint32_t vs_base = smem_u32(Vsm);
    auto issue_kv = [&](int kb, int stg) {
        uint32_t off = (uint32_t)stg * 64 * KLH * 2;
#pragma unroll
        for (int i = 0; i < 8; i++) {
            int idx = tid + i * 128;
            int r = idx >> 4, c8 = (idx & 15) * 8;
            size_t g = (size_t)(b * SEQ + kb * 64 + r) * D_MODEL + h * DKH + c8;
            uint32_t d = (uint32_t)(r * KLH + c8) * 2;
            cp_async16_ca(ks_base + off + d, K + g);
            cp_async16_ca(vs_base + off + d, V + g);
        }
    };

    issue_kv(0, 0); CP_COMMIT();

    float o[16][4] = {};
    float m0 = -1e30f, m1 = -1e30f, l0 = 0.f, l1 = 0.f;
    const float scale = 0.08838834764831845f;

    for (int kb = 0; kb < nkb; kb++) {
        CP_WAIT(0);
        __syncthreads();
        if (kb + 1 < nkb) issue_kv(kb + 1, (kb + 1) & 1);
        CP_COMMIT();
        uint32_t kst = ks_base + (uint32_t)(kb & 1) * 64 * KLH * 2;
        uint32_t vst = vs_base + (uint32_t)(kb & 1) * 64 * KLH * 2;

        float s[8][4] = {};
#pragma unroll
        for (int c2 = 0; c2 < 4; c2++) {
#pragma unroll
            for (int n0 = 0; n0 < 8; n0++) {
                uint32_t kf[4];
                ldsm_x4(kf, kst + (uint32_t)((n0 * 8 + r8) * KLH + c2 * 32 + m4 * 8) * 2);
                mma_f16(s[n0], afq[2 * c2],     kf);
                mma_f16(s[n0], afq[2 * c2 + 1], kf + 2);
            }
        }

        bool diag = (kb == qblk);
        int row0 = q0 + wid * 16 + qr, row1 = row0 + 8;
        float mt0 = -1e30f, mt1 = -1e30f;
#pragma unroll
        for (int nt = 0; nt < 8; nt++) {
            int col = kb * 64 + nt * 8 + 2 * qc;
            s[nt][0] *= scale; s[nt][1] *= scale;
            s[nt][2] *= scale; s[nt][3] *= scale;
            if (diag) {
                if (col > row0)     s[nt][0] = -1e30f;
                if (col + 1 > row0) s[nt][1] = -1e30f;
                if (col > row1)     s[nt][2] = -1e30f;
                if (col + 1 > row1) s[nt][3] = -1e30f;
            }
            mt0 = fmaxf(mt0, fmaxf(s[nt][0], s[nt][1]));
            mt1 = fmaxf(mt1, fmaxf(s[nt][2], s[nt][3]));
        }
#pragma unroll
        for (int off = 1; off < 4; off <<= 1) {
            mt0 = fmaxf(mt0, __shfl_xor_sync(0xffffffffu, mt0, off));
            mt1 = fmaxf(mt1, __shfl_xor_sync(0xffffffffu, mt1, off));
        }
        float mn0 = fmaxf(m0, mt0), mn1 = fmaxf(m1, mt1);
        float ls0 = 0.f, ls1 = 0.f;

        uint32_t afp[4][4];
#pragma unroll
        for (int nt = 0; nt < 8; nt++) {
            uint32_t h01 = f22u(__expf(s[nt][0] - mn0), __expf(s[nt][1] - mn0));
            uint32_t h23 = f22u(__expf(s[nt][2] - mn1), __expf(s[nt][3] - mn1));
            float2 f01 = __half22float2(*(__half2*)&h01);
            float2 f23 = __half22float2(*(__half2*)&h23);
            ls0 += f01.x + f01.y; ls1 += f23.x + f23.y;
            int ks = nt >> 1;
            if ((nt & 1) == 0) { afp[ks][0] = h01; afp[ks][1] = h23; }
            else               { afp[ks][2] = h01; afp[ks][3] = h23; }
        }
#pragma unroll
        for (int off = 1; off < 4; off <<= 1) {
            ls0 += __shfl_xor_sync(0xffffffffu, ls0, off);
            ls1 += __shfl_xor_sync(0xffffffffu, ls1, off);
        }
        float al0 = __expf(m0 - mn0), al1 = __expf(m1 - mn1);
        l0 = l0 * al0 + ls0; l1 = l1 * al1 + ls1;
        m0 = mn0; m1 = mn1;
#pragma unroll
        for (int nt = 0; nt < 16; nt++) {
            o[nt][0] *= al0; o[nt][1] *= al0;
            o[nt][2] *= al1; o[nt][3] *= al1;
        }

#pragma unroll
        for (int ks = 0; ks < 4; ks++) {
#pragma unroll
            for (int g = 0; g < 8; g++) {
                uint32_t vf[4];
                ldsm_x4_t(vf, vst + (uint32_t)((ks * 16 + (m4 & 1) * 8 + r8) * KLH
                                               + g * 16 + (m4 >> 1) * 8) * 2);
                mma_f16(o[2 * g],     afp[ks], vf);
                mma_f16(o[2 * g + 1], afp[ks], vf + 2);
            }
        }
    }

    float i0 = 1.f / l0, i1 = 1.f / l1;
    int r0 = b * SEQ + q0 + wid * 16 + qr;
#pragma unroll
    for (int nt = 0; nt < 16; nt++) {
        int cc = h * DKH + nt * 8 + 2 * qc;
        *(__half2*)(O + (size_t)r0 * D_MODEL + cc) =
            __floats2half2_rn(o[nt][0] * i0, o[nt][1] * i0);
        *(__half2*)(O + (size_t)(r0 + 8) * D_MODEL + cc) =
            __floats2half2_rn(o[nt][2] * i1, o[nt][3] * i1);
    }
}

// ---------------- launch ----------------
extern "C" void kernel_launch(void* const* d_in, const int* in_sizes, int n_in,
                              void* d_out, int out_size) {
    const float* x  = (const float*)d_in[0];
    const float* Wq = (const float*)d_in[1];
    const float* Wk = (const float*)d_in[2];
    const float* Wv = (const float*)d_in[3];
    const float* Wo = (const float*)d_in[4];
    const float* W1 = (const float*)d_in[5];
    const float* W2 = (const float*)d_in[6];
    const float* W3 = (const float*)d_in[7];
    const float* g1 = (const float*)d_in[8];
    const float* g2 = (const float*)d_in[9];
    float* out = (float*)d_out;

    float *xmid;
    __half *xnh, *ctxh, *ffh, *qh, *kh, *vh;
    __half *wqh, *wkh, *wvh, *woh, *w1h, *w2h, *w3h;
    cudaGetSymbolAddress((void**)&xmid, g_xmid);
    cudaGetSymbolAddress((void**)&xnh,  g_xn_h);
    cudaGetSymbolAddress((void**)&ctxh, g_ctx_h);
    cudaGetSymbolAddress((void**)&ffh,  g_ff_h);
    cudaGetSymbolAddress((void**)&qh,   g_qh);
    cudaGetSymbolAddress((void**)&kh,   g_kh);
    cudaGetSymbolAddress((void**)&vh,   g_vh);
    cudaGetSymbolAddress((void**)&wqh,  g_wq);
    cudaGetSymbolAddress((void**)&wkh,  g_wk);
    cudaGetSymbolAddress((void**)&wvh,  g_wv);
    cudaGetSymbolAddress((void**)&woh,  g_wo);
    cudaGetSymbolAddress((void**)&w1h,  g_w1);
    cudaGetSymbolAddress((void**)&w2h,  g_w2);
    cudaGetSymbolAddress((void**)&w3h,  g_w3);

    cudaFuncSetAttribute(gemm_mma<1>, cudaFuncAttributeMaxDynamicSharedMemorySize, GEMM_SMEM);
    cudaFuncSetAttribute(gemm_mma<3>, cudaFuncAttributeMaxDynamicSharedMemorySize, GEMM_SMEM);
    cudaFuncSetAttribute(gemm_qkv,    cudaFuncAttributeMaxDynamicSharedMemorySize, GEMM_SMEM);
    cudaFuncSetAttribute(gemm_w13,    cudaFuncAttributeMaxDynamicSharedMemorySize, GEMM_SMEM);
    cudaFuncSetAttribute(attn_f16,    cudaFuncAttributeMaxDynamicSharedMemorySize, ATT_SMEM);

    // ---- side stream for weight conversion (graph-capture fork/join) ----
    cudaStream_t s2;
    cudaStreamCreateWithFlags(&s2, cudaStreamNonBlocking);
    cudaEvent_t evFork, evQKV, evW;
    cudaEventCreateWithFlags(&evFork, cudaEventDisableTiming);
    cudaEventCreateWithFlags(&evQKV,  cudaEventDisableTiming);
    cudaEventCreateWithFlags(&evW,    cudaEventDisableTiming);

    cudaEventRecord(evFork, 0);
    cudaStreamWaitEvent(s2, evFork, 0);

    const int CT = 256;
    int nDM = D_MODEL * D_MODEL / 4, nFF = DFF * D_MODEL / 4;
    f2h_kernel<<<(nDM + CT - 1) / CT, CT, 0, s2>>>((const float4*)Wq, (__half2*)wqh, nDM);
    f2h_kernel<<<(nDM + CT - 1) / CT, CT, 0, s2>>>((const float4*)Wk, (__half2*)wkh, nDM);
    f2h_kernel<<<(nDM + CT - 1) / CT, CT, 0, s2>>>((const float4*)Wv, (__half2*)wvh, nDM);
    cudaEventRecord(evQKV, s2);
    f2h_kernel<<<(nDM + CT - 1) / CT, CT, 0, s2>>>((const float4*)Wo, (__half2*)woh, nDM);
    f2h_kernel<<<(nFF + CT - 1) / CT, CT, 0, s2>>>((const float4*)W1, (__half2*)w1h, nFF);
    f2h_kernel<<<(nFF + CT - 1) / CT, CT, 0, s2>>>((const float4*)W3, (__half2*)w3h, nFF);
    f2h_kernel<<<(nFF + CT - 1) / CT, CT, 0, s2>>>((const float4*)W2, (__half2*)w2h, nFF);
    cudaEventRecord(evW, s2);

    dim3 blk(256);
    rmsnorm_kernel<<<M_TOK, 256>>>(x, g1, xnh);
    rope_table_kernel<<<(SEQ * 64 + 255) / 256, 256>>>();
    cudaStreamWaitEvent(0, evQKV, 0);
    dim3 gq(D_MODEL / GBN, M_TOK / GBM, 3);
    gemm_qkv<<<gq, blk, GEMM_SMEM>>>(xnh);
    dim3 gattn(SEQ / 64, BATCH * NHEAD);
    attn_f16<<<gattn, 128, ATT_SMEM>>>(qh, kh, vh, ctxh);
    cudaStreamWaitEvent(0, evW, 0);
    dim3 gdm(D_MODEL / GBN, M_TOK / GBM);
    gemm_mma<1><<<gdm, blk, GEMM_SMEM>>>(ctxh, woh, x, xmid, M_TOK, D_MODEL, D_MODEL);
    rmsnorm_kernel<<<M_TOK, 256>>>(xmid, g2, xnh);
    dim3 gw13(DFF / 64, M_TOK / 128);
    gemm_w13<<<gw13, blk, GEMM_SMEM>>>(xnh, ffh);
    gemm_mma<1><<<gdm, blk, GEMM_SMEM>>>(ffh, w2h, xmid, out, M_TOK, D_MODEL, DFF);
}

// round 17
// speedup vs baseline: 1.0801x; 1.0801x over previous
#include <cuda_runtime.h>
#include <cuda_fp16.h>
#include <math.h>
#include <stdint.h>

#define D_MODEL 2048
#define NHEAD   16
#define DKH     128
#define DFF     5632
#define SEQ     2048
#define BATCH   2
#define M_TOK   (BATCH*SEQ)   // 4096

// ---------------- scratch ----------------
__device__ float  g_xmid[(size_t)M_TOK*D_MODEL];
__device__ __half g_xn_h [(size_t)M_TOK*D_MODEL];
__device__ __half g_ctx_h[(size_t)M_TOK*D_MODEL];
__device__ __half g_ff_h [(size_t)M_TOK*DFF];
__device__ __half g_qh[(size_t)M_TOK*D_MODEL];
__device__ __half g_kh[(size_t)M_TOK*D_MODEL];
__device__ __half g_vh[(size_t)M_TOK*D_MODEL];
__device__ __half g_wq[(size_t)D_MODEL*D_MODEL];
__device__ __half g_wk[(size_t)D_MODEL*D_MODEL];
__device__ __half g_wv[(size_t)D_MODEL*D_MODEL];
__device__ __half g_wo[(size_t)D_MODEL*D_MODEL];
__device__ __half g_w1[(size_t)DFF*D_MODEL];
__device__ __half g_w2[(size_t)D_MODEL*DFF];
__device__ __half g_w3[(size_t)DFF*D_MODEL];
__device__ float  g_rsin[SEQ*64];
__device__ float  g_rcos[SEQ*64];

// ================= helpers =================
__device__ __forceinline__ void mma_f16(float* d, const uint32_t* a, const uint32_t* b) {
    asm volatile(
        "mma.sync.aligned.m16n8k16.row.col.f32.f16.f16.f32 "
        "{%0,%1,%2,%3}, {%4,%5,%6,%7}, {%8,%9}, {%0,%1,%2,%3};"
        : "+f"(d[0]), "+f"(d[1]), "+f"(d[2]), "+f"(d[3])
        : "r"(a[0]), "r"(a[1]), "r"(a[2]), "r"(a[3]),
          "r"(b[0]), "r"(b[1]));
}
__device__ __forceinline__ uint32_t smem_u32(const void* p) {
    uint32_t a;
    asm("{ .reg .u64 t; cvta.to.shared.u64 t, %1; cvt.u32.u64 %0, t; }"
        : "=r"(a) : "l"(p));
    return a;
}
__device__ __forceinline__ void cp_async16(uint32_t dst, const void* src) {
    asm volatile("cp.async.cg.shared.global [%0], [%1], 16;" :: "r"(dst), "l"(src));
}
#define CP_COMMIT()  asm volatile("cp.async.commit_group;" ::: "memory")
#define CP_WAIT(N)   asm volatile("cp.async.wait_group %0;" :: "n"(N) : "memory")

__device__ __forceinline__ void ldsm_x4(uint32_t* r, uint32_t a) {
    asm volatile("ldmatrix.sync.aligned.m8n8.x4.shared.b16 {%0,%1,%2,%3}, [%4];"
                 : "=r"(r[0]), "=r"(r[1]), "=r"(r[2]), "=r"(r[3]) : "r"(a));
}
__device__ __forceinline__ void ldsm_x4_t(uint32_t* r, uint32_t a) {
    asm volatile("ldmatrix.sync.aligned.m8n8.x4.trans.shared.b16 {%0,%1,%2,%3}, [%4];"
                 : "=r"(r[0]), "=r"(r[1]), "=r"(r[2]), "=r"(r[3]) : "r"(a));
}
__device__ __forceinline__ uint32_t f22u(float a, float b) {
    __half2 h = __floats2half2_rn(a, b);
    return *(uint32_t*)&h;
}

// ---------------- fp32 -> fp16 convert ----------------
__global__ void f2h_kernel(const float4* __restrict__ in, __half2* __restrict__ out, int n4) {
    int i = blockIdx.x * blockDim.x + threadIdx.x;
    if (i >= n4) return;
    float4 v = in[i];
    out[2 * i]     = __floats2half2_rn(v.x, v.y);
    out[2 * i + 1] = __floats2half2_rn(v.z, v.w);
}

// batched Wq/Wk/Wv convert (blockIdx.y selects weight)
__global__ void f2h3_kernel(const float4* __restrict__ wq,
                            const float4* __restrict__ wk,
                            const float4* __restrict__ wv, int n4) {
    int i = blockIdx.x * blockDim.x + threadIdx.x;
    if (i >= n4) return;
    const float4* in = blockIdx.y == 0 ? wq : (blockIdx.y == 1 ? wk : wv);
    __half2* out = (__half2*)(blockIdx.y == 0 ? g_wq : (blockIdx.y == 1 ? g_wk : g_wv));
    float4 v = in[i];
    out[2 * i]     = __floats2half2_rn(v.x, v.y);
    out[2 * i + 1] = __floats2half2_rn(v.z, v.w);
}

// ================= fp16 GEMM, 128x128 tiles, BK=64, 3-stage, 2 CTAs/SM ======
#define GBM 128
#define GBN 128
#define LDH  72
#define GSTG 3
#define GEMM_SMEM (GSTG*(GBM+GBN)*LDH*2)

template<int EPI>
__device__ __forceinline__ void gemm_body(
        const __half* __restrict__ A,
        const __half* __restrict__ W,
        const void* __restrict__ res,
        void* __restrict__ CO,
        int M, int N, int K, int ropef) {
    extern __shared__ char smc[];
    __half* As = (__half*)smc;
    __half* Bs = As + GSTG * GBM * LDH;

    int tid  = threadIdx.x;
    int lane = tid & 31, wid = tid >> 5;
    int wmb = (wid >> 2) * 64, wnb = (wid & 3) * 32;
    int bm = blockIdx.y * GBM, bn = blockIdx.x * GBN;
    int m4 = lane >> 3, r8 = lane & 7;

    uint32_t as_base = smem_u32(As);
    uint32_t bs_base = smem_u32(Bs);

    auto issue_stage = [&](int tile, int stg) {
        uint32_t aoff = (uint32_t)stg * GBM * LDH * 2;
        uint32_t boff = (uint32_t)stg * GBN * LDH * 2;
        const __half* a2 = A + (size_t)bm * K + tile * 64;
        const __half* w2 = W + (size_t)bn * K + tile * 64;
#pragma unroll
        for (int i = 0; i < 4; i++) {
            int idx = tid + i * 256;
            int r = idx >> 3, c = (idx & 7) * 8;
            cp_async16(as_base + aoff + (uint32_t)(r * LDH + c) * 2,
                       a2 + (size_t)r * K + c);
            cp_async16(bs_base + boff + (uint32_t)(r * LDH + c) * 2,
                       w2 + (size_t)r * K + c);
        }
    };

    int nk = K >> 6;
    issue_stage(0, 0); CP_COMMIT();
    issue_stage(1, 1); CP_COMMIT();

    float acc[4][4][4] = {};
    int qr = lane >> 2, qc = lane & 3;

    int stg = 0;
    for (int kt = 0; kt < nk; kt++) {
        CP_WAIT(1);
        __syncthreads();
        uint32_t aS = as_base + (uint32_t)stg * GBM * LDH * 2;
        uint32_t bS = bs_base + (uint32_t)stg * GBN * LDH * 2;

#pragma unroll
        for (int kh = 0; kh < 2; kh++) {
            uint32_t bf[4][4];
#pragma unroll
            for (int nt = 0; nt < 4; nt++) {
                int n0 = wnb + nt * 8 + r8;
                ldsm_x4(bf[nt], bS + (uint32_t)(n0 * LDH + kh * 32 + m4 * 8) * 2);
            }
#pragma unroll
            for (int k2 = 0; k2 < 2; k2++) {
                int ks = kh * 2 + k2;
                uint32_t af[4][4];
#pragma unroll
                for (int mt = 0; mt < 4; mt++) {
                    int r0 = wmb + mt * 16 + (m4 & 1) * 8 + r8;
                    ldsm_x4(af[mt], aS + (uint32_t)(r0 * LDH + ks * 16 + (m4 >> 1) * 8) * 2);
                }
#pragma unroll
                for (int mt = 0; mt < 4; mt++)
#pragma unroll
                    for (int nt = 0; nt < 4; nt++)
                        mma_f16(acc[mt][nt], af[mt], &bf[nt][2 * k2]);
            }
        }
        int nstg = stg + 2; if (nstg >= GSTG) nstg -= GSTG;
        if (kt + 2 < nk) issue_stage(kt + 2, nstg);
        CP_COMMIT();
        stg = stg + 1 == GSTG ? 0 : stg + 1;
    }

#pragma unroll
    for (int mt = 0; mt < 4; mt++) {
        int r0 = bm + wmb + mt * 16 + qr;
#pragma unroll
        for (int nt = 0; nt < 4; nt++) {
            int cc = bn + wnb + nt * 8 + 2 * qc;
            size_t i0 = (size_t)r0 * N + cc;
            size_t i1 = (size_t)(r0 + 8) * N + cc;
            if (EPI == 1) {
                const float* rf = (const float*)res;
                float* C = (float*)CO;
                float2 rr0 = *(const float2*)(rf + i0);
                float2 rr1 = *(const float2*)(rf + i1);
                *(float2*)(C + i0) = make_float2(acc[mt][nt][0] + rr0.x,
                                                 acc[mt][nt][1] + rr0.y);
                *(float2*)(C + i1) = make_float2(acc[mt][nt][2] + rr1.x,
                                                 acc[mt][nt][3] + rr1.y);
            } else {
                __half* C = (__half*)CO;
                float a0 = acc[mt][nt][0], a1 = acc[mt][nt][1];
                float a2 = acc[mt][nt][2], a3 = acc[mt][nt][3];
                if (ropef) {
                    int s0 = r0 & (SEQ - 1), s1 = (r0 + 8) & (SEQ - 1);
                    int j  = (cc & 127) >> 1;
                    float sn0 = g_rsin[s0 * 64 + j], cs0 = g_rcos[s0 * 64 + j];
                    float sn1 = g_rsin[s1 * 64 + j], cs1 = g_rcos[s1 * 64 + j];
                    *(__half2*)(C + i0) = __floats2half2_rn(a0 * cs0 - a1 * sn0,
                                                            a0 * sn0 + a1 * cs0);
                    *(__half2*)(C + i1) = __floats2half2_rn(a2 * cs1 - a3 * sn1,
                                                            a2 * sn1 + a3 * cs1);
                } else {
                    *(__half2*)(C + i0) = __floats2half2_rn(a0, a1);
                    *(__half2*)(C + i1) = __floats2half2_rn(a2, a3);
                }
            }
        }
    }
}

template<int EPI>
__global__ __launch_bounds__(256, 2) void gemm_mma(
        const __half* __restrict__ A, const __half* __restrict__ W,
        const void* __restrict__ res, void* __restrict__ CO,
        int M, int N, int K) {
    gemm_body<EPI>(A, W, res, CO, M, N, K, 0);
}

__global__ __launch_bounds__(256, 2) void gemm_qkv(const __half* __restrict__ A) {
    int z = blockIdx.z;
    const __half* W = z == 0 ? g_wq : (z == 1 ? g_wk : g_wv);
    __half* C = z == 0 ? g_qh : (z == 1 ? g_kh : g_vh);
    gemm_body<3>(A, W, nullptr, C, M_TOK, D_MODEL, D_MODEL, z < 2);
}

// ========== fused W1+W3 GEMM: ff = silu(W1 xn) * (W3 xn), BK=64 =============
__global__ __launch_bounds__(256, 2) void gemm_w13(const __half* __restrict__ A,
                                                   __half* __restrict__ FF) {
    extern __shared__ char smc[];
    __half* As  = (__half*)smc;
    __half* B1s = As  + GSTG * 128 * LDH;
    __half* B3s = B1s + GSTG * 64 * LDH;

    const int K = D_MODEL, N = DFF;
    int tid  = threadIdx.x;
    int lane = tid & 31, wid = tid >> 5;
    int wmb = (wid >> 2) * 64, wnb = (wid & 3) * 16;
    int bm = blockIdx.y * 128, bn = blockIdx.x * 64;
    int m4 = lane >> 3, r8 = lane & 7;

    uint32_t as_base  = smem_u32(As);
    uint32_t b1_base  = smem_u32(B1s);
    uint32_t b3_base  = smem_u32(B3s);

    auto issue_stage = [&](int tile, int stg) {
        uint32_t aoff = (uint32_t)stg * 128 * LDH * 2;
        uint32_t boff = (uint32_t)stg * 64 * LDH * 2;
        const __half* a2 = A    + (size_t)bm * K + tile * 64;
        const __half* w1 = g_w1 + (size_t)bn * K + tile * 64;
        const __half* w3 = g_w3 + (size_t)bn * K + tile * 64;
#pragma unroll
        for (int i = 0; i < 4; i++) {
            int idx = tid + i * 256;
            int r = idx >> 3, c = (idx & 7) * 8;
            cp_async16(as_base + aoff + (uint32_t)(r * LDH + c) * 2,
                       a2 + (size_t)r * K + c);
        }
#pragma unroll
        for (int i = 0; i < 2; i++) {
            int idx = tid + i * 256;
            int r = idx >> 3, c = (idx & 7) * 8;
            uint32_t d = (uint32_t)(r * LDH + c) * 2;
            cp_async16(b1_base + boff + d, w1 + (size_t)r * K + c);
            cp_async16(b3_base + boff + d, w3 + (size_t)r * K + c);
        }
    };

    int nk = K >> 6;
    issue_stage(0, 0); CP_COMMIT();
    issue_stage(1, 1); CP_COMMIT();

    float acc1[4][2][4] = {}, acc3[4][2][4] = {};
    int qr = lane >> 2, qc = lane & 3;

    int stg = 0;
    for (int kt = 0; kt < nk; kt++) {
        CP_WAIT(1);
        __syncthreads();
        uint32_t aS  = as_base + (uint32_t)stg * 128 * LDH * 2;
        uint32_t b1S = b1_base + (uint32_t)stg * 64 * LDH * 2;
        uint32_t b3S = b3_base + (uint32_t)stg * 64 * LDH * 2;

#pragma unroll
        for (int kh = 0; kh < 2; kh++) {
            uint32_t b1f[2][4], b3f[2][4];
#pragma unroll
            for (int nt = 0; nt < 2; nt++) {
                int n0 = wnb + nt * 8 + r8;
                ldsm_x4(b1f[nt], b1S + (uint32_t)(n0 * LDH + kh * 32 + m4 * 8) * 2);
                ldsm_x4(b3f[nt], b3S + (uint32_t)(n0 * LDH + kh * 32 + m4 * 8) * 2);
            }
#pragma unroll
            for (int k2 = 0; k2 < 2; k2++) {
                int ks = kh * 2 + k2;
                uint32_t af[4][4];
#pragma unroll
                for (int mt = 0; mt < 4; mt++) {
                    int r0 = wmb + mt * 16 + (m4 & 1) * 8 + r8;
                    ldsm_x4(af[mt], aS + (uint32_t)(r0 * LDH + ks * 16 + (m4 >> 1) * 8) * 2);
                }
#pragma unroll
                for (int mt = 0; mt < 4; mt++)
#pragma unroll
                    for (int nt = 0; nt < 2; nt++) {
                        mma_f16(acc1[mt][nt], af[mt], &b1f[nt][2 * k2]);
                        mma_f16(acc3[mt][nt], af[mt], &b3f[nt][2 * k2]);
                    }
            }
        }
        int nstg = stg + 2; if (nstg >= GSTG) nstg -= GSTG;
        if (kt + 2 < nk) issue_stage(kt + 2, nstg);
        CP_COMMIT();
        stg = stg + 1 == GSTG ? 0 : stg + 1;
    }

#pragma unroll
    for (int mt = 0; mt < 4; mt++) {
        int r0 = bm + wmb + mt * 16 + qr;
#pragma unroll
        for (int nt = 0; nt < 2; nt++) {
            int cc = bn + wnb + nt * 8 + 2 * qc;
            size_t i0 = (size_t)r0 * N + cc;
            size_t i1 = (size_t)(r0 + 8) * N + cc;
            float a0 = acc1[mt][nt][0], a1 = acc1[mt][nt][1];
            float a2 = acc1[mt][nt][2], a3 = acc1[mt][nt][3];
            float v0 = acc3[mt][nt][0] * (a0 / (1.f + __expf(-a0)));
            float v1 = acc3[mt][nt][1] * (a1 / (1.f + __expf(-a1)));
            float v2 = acc3[mt][nt][2] * (a2 / (1.f + __expf(-a2)));
            float v3 = acc3[mt][nt][3] * (a3 / (1.f + __expf(-a3)));
            *(__half2*)(FF + i0) = __floats2half2_rn(v0, v1);
            *(__half2*)(FF + i1) = __floats2half2_rn(v2, v3);
        }
    }
}

// ---------------- RMSNorm (float4 loads, writes half) ----------------
__global__ void rmsnorm_kernel(const float* __restrict__ x,
                               const float* __restrict__ g,
                               __half* __restrict__ out) {
    int row = blockIdx.x;
    const float4* xr = (const float4*)(x + (size_t)row * D_MODEL);
    float4 v[2];
    v[0] = xr[threadIdx.x];
    v[1] = xr[threadIdx.x + 256];
    float s = v[0].x*v[0].x + v[0].y*v[0].y + v[0].z*v[0].z + v[0].w*v[0].w
            + v[1].x*v[1].x + v[1].y*v[1].y + v[1].z*v[1].z + v[1].w*v[1].w;
    __shared__ float red[32];
    for (int o = 16; o; o >>= 1) s += __shfl_down_sync(0xffffffffu, s, o);
    if ((threadIdx.x & 31) == 0) red[threadIdx.x >> 5] = s;
    __syncthreads();
    if (threadIdx.x < 32) {
        float t = (threadIdx.x < 8) ? red[threadIdx.x] : 0.f;
        for (int o = 4; o; o >>= 1) t += __shfl_down_sync(0xffffffffu, t, o);
        if (threadIdx.x == 0) red[0] = t;
    }
    __syncthreads();
    float rinv = rsqrtf(red[0] * (1.0f / D_MODEL) + 1e-5f);
    __half2* orow = (__half2*)(out + (size_t)row * D_MODEL);
    const float4* g4 = (const float4*)g;
#pragma unroll
    for (int i = 0; i < 2; i++) {
        float4 gv = g4[threadIdx.x + i * 256];
        orow[(threadIdx.x + i * 256) * 2]     =
            __floats2half2_rn(v[i].x * gv.x * rinv, v[i].y * gv.y * rinv);
        orow[(threadIdx.x + i * 256) * 2 + 1] =
            __floats2half2_rn(v[i].z * gv.z * rinv, v[i].w * gv.w * rinv);
    }
}

// ---------------- RoPE tables ----------------
__global__ void rope_table_kernel() {
    int idx = blockIdx.x * blockDim.x + threadIdx.x;
    if (idx >= SEQ * 64) return;
    int j = idx & 63, s = idx >> 6;
    double inv = exp(-(double)j * (9.210340371976184 / 64.0));
    double ang = fmod((double)s * inv, 6.283185307179586476925286766559);
    float fa = (float)ang;
    g_rsin[idx] = sinf(fa);
    g_rcos[idx] = cosf(fa);
}

// ---------------- fp16 flash attention: BQ=64, 128 threads, multi-CTA/SM ----
#define QLD 136
#define KLH 136
#define ATT_SMEM ((2*64*KLH + 2*64*KLH) * 2)

__global__ __launch_bounds__(128) void attn_f16(
        const __half* __restrict__ Q,
        const __half* __restrict__ K,
        const __half* __restrict__ V,
        __half* __restrict__ O) {
    extern __shared__ __half smh[];
    __half* Qst = smh;
    __half* Ksm = smh;
    __half* Vsm = Ksm + 2 * 64 * KLH;

    int tid = threadIdx.x;
    int lane = tid & 31, wid = tid >> 5;
    int qr = lane >> 2, qc = lane & 3;
    int bh = blockIdx.y;
    int b = bh >> 4, h = bh & 15;
    int qblk = gridDim.x - 1 - blockIdx.x;
    int q0 = qblk * 64;
    int nkb = qblk + 1;
    int m4 = lane >> 3;
    int r8 = lane & 7;

    for (int i = tid; i < 64 * 16; i += 128) {
        int r = i >> 4, c8 = (i & 15) * 8;
        *(uint4*)(Qst + r * QLD + c8) =
            *(const uint4*)(Q + (size_t)(b * SEQ + q0 + r) * D_MODEL + h * DKH + c8);
    }
    __syncthreads();
    uint32_t afq[8][4];
    {
        uint32_t qb_ = smem_u32(Qst);
        int row = wid * 16 + (m4 & 1) * 8 + r8;
#pragma unroll
        for (int ks = 0; ks < 8; ks++)
            ldsm_x4(afq[ks], qb_ + (uint32_t)(row * QLD + ks * 16 + (m4 >> 1) * 8) * 2);
    }
    __syncthreads();

    uint32_t ks_base = smem_u32(Ksm);
    uint32_t vs_base = smem_u32(Vsm);
    auto issue_kv = [&](int kb, int stg) {
        uint32_t off = (uint32_t)stg * 64 * KLH * 2;
#pragma unroll
        for (int i = 0; i < 8; i++) {
            int idx = tid + i * 128;
            int r = idx >> 4, c8 = (idx & 15) * 8;
            size_t g = (size_t)(b * SEQ + kb * 64 + r) * D_MODEL + h * DKH + c8;
            uint32_t d = (uint32_t)(r * KLH + c8) * 2;
            cp_async16(ks_base + off + d, K + g);
            cp_async16(vs_base + off + d, V + g);
        }
    };

    issue_kv(0, 0); CP_COMMIT();

    float o[16][4] = {};
    float m0 = -1e30f, m1 = -1e30f, l0 = 0.f, l1 = 0.f;
    const float scale = 0.08838834764831845f;

    for (int kb = 0; kb < nkb; kb++) {
        CP_WAIT(0);
        __syncthreads();
        if (kb + 1 < nkb) issue_kv(kb + 1, (kb + 1) & 1);
        CP_COMMIT();
        uint32_t kst = ks_base + (uint32_t)(kb & 1) * 64 * KLH * 2;
        uint32_t vst = vs_base + (uint32_t)(kb & 1) * 64 * KLH * 2;

        float s[8][4] = {};
#pragma unroll
        for (int c2 = 0; c2 < 4; c2++) {
#pragma unroll
            for (int n0 = 0; n0 < 8; n0++) {
                uint32_t kf[4];
                ldsm_x4(kf, kst + (uint32_t)((n0 * 8 + r8) * KLH + c2 * 32 + m4 * 8) * 2);
                mma_f16(s[n0], afq[2 * c2],     kf);
                mma_f16(s[n0], afq[2 * c2 + 1], kf + 2);
            }
        }

        bool diag = (kb == qblk);
        int row0 = q0 + wid * 16 + qr, row1 = row0 + 8;
        float mt0 = -1e30f, mt1 = -1e30f;
#pragma unroll
        for (int nt = 0; nt < 8; nt++) {
            int col = kb * 64 + nt * 8 + 2 * qc;
            s[nt][0] *= scale; s[nt][1] *= scale;
            s[nt][2] *= scale; s[nt][3] *= scale;
            if (diag) {
                if (col > row0)     s[nt][0] = -1e30f;
                if (col + 1 > row0) s[nt][1] = -1e30f;
                if (col > row1)     s[nt][2] = -1e30f;
                if (col + 1 > row1) s[nt][3] = -1e30f;
            }
            mt0 = fmaxf(mt0, fmaxf(s[nt][0], s[nt][1]));
            mt1 = fmaxf(mt1, fmaxf(s[nt][2], s[nt][3]));
        }
#pragma unroll
        for (int off = 1; off < 4; off <<= 1) {
            mt0 = fmaxf(mt0, __shfl_xor_sync(0xffffffffu, mt0, off));
            mt1 = fmaxf(mt1, __shfl_xor_sync(0xffffffffu, mt1, off));
        }
        float mn0 = fmaxf(m0, mt0), mn1 = fmaxf(m1, mt1);
        float ls0 = 0.f, ls1 = 0.f;

        uint32_t afp[4][4];
#pragma unroll
        for (int nt = 0; nt < 8; nt++) {
            uint32_t h01 = f22u(__expf(s[nt][0] - mn0), __expf(s[nt][1] - mn0));
            uint32_t h23 = f22u(__expf(s[nt][2] - mn1), __expf(s[nt][3] - mn1));
            float2 f01 = __half22float2(*(__half2*)&h01);
            float2 f23 = __half22float2(*(__half2*)&h23);
            ls0 += f01.x + f01.y; ls1 += f23.x + f23.y;
            int ks = nt >> 1;
            if ((nt & 1) == 0) { afp[ks][0] = h01; afp[ks][1] = h23; }
            else               { afp[ks][2] = h01; afp[ks][3] = h23; }
        }
#pragma unroll
        for (int off = 1; off < 4; off <<= 1) {
            ls0 += __shfl_xor_sync(0xffffffffu, ls0, off);
            ls1 += __shfl_xor_sync(0xffffffffu, ls1, off);
        }
        float al0 = __expf(m0 - mn0), al1 = __expf(m1 - mn1);
        l0 = l0 * al0 + ls0; l1 = l1 * al1 + ls1;
        m0 = mn0; m1 = mn1;
#pragma unroll
        for (int nt = 0; nt < 16; nt++) {
            o[nt][0] *= al0; o[nt][1] *= al0;
            o[nt][2] *= al1; o[nt][3] *= al1;
        }

#pragma unroll
        for (int ks = 0; ks < 4; ks++) {
#pragma unroll
            for (int g = 0; g < 8; g++) {
                uint32_t vf[4];
                ldsm_x4_t(vf, vst + (uint32_t)((ks * 16 + (m4 & 1) * 8 + r8) * KLH
                                               + g * 16 + (m4 >> 1) * 8) * 2);
                mma_f16(o[2 * g],     afp[ks], vf);
                mma_f16(o[2 * g + 1], afp[ks], vf + 2);
            }
        }
    }

    float i0 = 1.f / l0, i1 = 1.f / l1;
    int r0 = b * SEQ + q0 + wid * 16 + qr;
#pragma unroll
    for (int nt = 0; nt < 16; nt++) {
        int cc = h * DKH + nt * 8 + 2 * qc;
        *(__half2*)(O + (size_t)r0 * D_MODEL + cc) =
            __floats2half2_rn(o[nt][0] * i0, o[nt][1] * i0);
        *(__half2*)(O + (size_t)(r0 + 8) * D_MODEL + cc) =
            __floats2half2_rn(o[nt][2] * i1, o[nt][3] * i1);
    }
}

// ---------------- launch ----------------
extern "C" void kernel_launch(void* const* d_in, const int* in_sizes, int n_in,
                              void* d_out, int out_size) {
    const float* x  = (const float*)d_in[0];
    const float* Wq = (const float*)d_in[1];
    const float* Wk = (const float*)d_in[2];
    const float* Wv = (const float*)d_in[3];
    const float* Wo = (const float*)d_in[4];
    const float* W1 = (const float*)d_in[5];
    const float* W2 = (const float*)d_in[6];
    const float* W3 = (const float*)d_in[7];
    const float* g1 = (const float*)d_in[8];
    const float* g2 = (const float*)d_in[9];
    float* out = (float*)d_out;

    float *xmid;
    __half *xnh, *ctxh, *ffh, *qh, *kh, *vh;
    __half *woh, *w1h, *w2h, *w3h;
    cudaGetSymbolAddress((void**)&xmid, g_xmid);
    cudaGetSymbolAddress((void**)&xnh,  g_xn_h);
    cudaGetSymbolAddress((void**)&ctxh, g_ctx_h);
    cudaGetSymbolAddress((void**)&ffh,  g_ff_h);
    cudaGetSymbolAddress((void**)&qh,   g_qh);
    cudaGetSymbolAddress((void**)&kh,   g_kh);
    cudaGetSymbolAddress((void**)&vh,   g_vh);
    cudaGetSymbolAddress((void**)&woh,  g_wo);
    cudaGetSymbolAddress((void**)&w1h,  g_w1);
    cudaGetSymbolAddress((void**)&w2h,  g_w2);
    cudaGetSymbolAddress((void**)&w3h,  g_w3);

    cudaFuncSetAttribute(gemm_mma<1>, cudaFuncAttributeMaxDynamicSharedMemorySize, GEMM_SMEM);
    cudaFuncSetAttribute(gemm_mma<3>, cudaFuncAttributeMaxDynamicSharedMemorySize, GEMM_SMEM);
    cudaFuncSetAttribute(gemm_qkv,    cudaFuncAttributeMaxDynamicSharedMemorySize, GEMM_SMEM);
    cudaFuncSetAttribute(gemm_w13,    cudaFuncAttributeMaxDynamicSharedMemorySize, GEMM_SMEM);
    cudaFuncSetAttribute(attn_f16,    cudaFuncAttributeMaxDynamicSharedMemorySize, ATT_SMEM);

    // ---- side stream for weight conversion (graph-capture fork/join) ----
    cudaStream_t s2;
    cudaStreamCreateWithFlags(&s2, cudaStreamNonBlocking);
    cudaEvent_t evFork, evQKV, evW;
    cudaEventCreateWithFlags(&evFork, cudaEventDisableTiming);
    cudaEventCreateWithFlags(&evQKV,  cudaEventDisableTiming);
    cudaEventCreateWithFlags(&evW,    cudaEventDisableTiming);

    cudaEventRecord(evFork, 0);
    cudaStreamWaitEvent(s2, evFork, 0);

    const int CT = 256;
    int nDM = D_MODEL * D_MODEL / 4, nFF = DFF * D_MODEL / 4;
    dim3 g3((nDM + CT - 1) / CT, 3);
    f2h3_kernel<<<g3, CT, 0, s2>>>((const float4*)Wq, (const float4*)Wk,
                                   (const float4*)Wv, nDM);
    cudaEventRecord(evQKV, s2);
    f2h_kernel<<<(nDM + CT - 1) / CT, CT, 0, s2>>>((const float4*)Wo, (__half2*)woh, nDM);
    f2h_kernel<<<(nFF + CT - 1) / CT, CT, 0, s2>>>((const float4*)W1, (__half2*)w1h, nFF);
    f2h_kernel<<<(nFF + CT - 1) / CT, CT, 0, s2>>>((const float4*)W3, (__half2*)w3h, nFF);
    f2h_kernel<<<(nFF + CT - 1) / CT, CT, 0, s2>>>((const float4*)W2, (__half2*)w2h, nFF);
    cudaEventRecord(evW, s2);

    dim3 blk(256);
    rmsnorm_kernel<<<M_TOK, 256>>>(x, g1, xnh);
    rope_table_kernel<<<(SEQ * 64 + 255) / 256, 256>>>();
    cudaStreamWaitEvent(0, evQKV, 0);
    dim3 gq(D_MODEL / GBN, M_TOK / GBM, 3);
    gemm_qkv<<<gq, blk, GEMM_SMEM>>>(xnh);
    dim3 gattn(SEQ / 64, BATCH * NHEAD);
    attn_f16<<<gattn, 128, ATT_SMEM>>>(qh, kh, vh, ctxh);
    cudaStreamWaitEvent(0, evW, 0);
    dim3 gdm(D_MODEL / GBN, M_TOK / GBM);
    gemm_mma<1><<<gdm, blk, GEMM_SMEM>>>(ctxh, woh, x, xmid, M_TOK, D_MODEL, D_MODEL);
    rmsnorm_kernel<<<M_TOK, 256>>>(xmid, g2, xnh);
    dim3 gw13(DFF / 64, M_TOK / 128);
    gemm_w13<<<gw13, blk, GEMM_SMEM>>>(xnh, ffh);
    gemm_mma<1><<<gdm, blk, GEMM_SMEM>>>(ffh, w2h, xmid, out, M_TOK, D_MODEL, DFF);
}